// round 11
// baseline (speedup 1.0000x reference)
#include <cuda_runtime.h>
#include <cuda_bf16.h>
#include <cuda_fp16.h>
#include <cstdint>
#include <cstddef>

// ---------------------------------------------------------------------------
// SparseGraphLearn:
//   h = inputs @ weight          [M=100000,256] @ [256,128]  fp32
//   edge_weight = relu(|h[e0]-h[e1]| @ a)   [E]
// d_out = [ h | edge_weight ]
//
// GEMM: mma.sync m16n8k16 bf16, truncation 2-term split (3 cross products).
//   All global->smem traffic via cp.async (double-buffered A raw staging +
//   B split tiles); convert reads smem. Low register pressure, no spills.
// Edge: gathers from fp16 shadow of h.
// ---------------------------------------------------------------------------

#define KTOT 256
#define NTOT 128
#define MTILE 128
#define KCH 64
#define LDS_W 36            // split-tile row stride in words (4 mod 32)
#define ARAW_W 68           // raw A staging row stride in words (4 mod 32)
#define NMAX 100000

// smem layout (bytes)
#define S_AHI    0
#define S_AMID   18432
#define S_BT0    36864          // B tiles buffer 0: hi(18432)+mid(18432)
#define B_BUF    36864
#define B_MID    18432
#define S_ARAW0  110592         // raw A staging: 128*68*4 = 34816 each
#define ARAW_BUF 34816
#define S_TOTAL  180224

__device__ __nv_bfloat16 g_whi[NTOT * KTOT];   // [n][k]
__device__ __nv_bfloat16 g_wmid[NTOT * KTOT];
__device__ __half        g_h16[(size_t)NMAX * NTOT];

__device__ __forceinline__ void mma_bf16(float* d, const uint32_t* a, const uint32_t* b) {
    asm volatile(
        "mma.sync.aligned.m16n8k16.row.col.f32.bf16.bf16.f32 "
        "{%0,%1,%2,%3}, {%4,%5,%6,%7}, {%8,%9}, {%0,%1,%2,%3};"
        : "+f"(d[0]), "+f"(d[1]), "+f"(d[2]), "+f"(d[3])
        : "r"(a[0]), "r"(a[1]), "r"(a[2]), "r"(a[3]), "r"(b[0]), "r"(b[1]));
}

__device__ __forceinline__ void ldsm4(uint32_t* r, uint32_t addr) {
    asm volatile("ldmatrix.sync.aligned.m8n8.x4.shared.b16 {%0,%1,%2,%3}, [%4];"
        : "=r"(r[0]), "=r"(r[1]), "=r"(r[2]), "=r"(r[3]) : "r"(addr));
}

__device__ __forceinline__ void cp16(uint32_t dst, const void* src, int sz) {
    asm volatile("cp.async.cg.shared.global [%0], [%1], 16, %2;"
        :: "r"(dst), "l"(src), "r"(sz) : "memory");
}
#define CP_COMMIT() asm volatile("cp.async.commit_group;" ::: "memory")
#define CP_WAIT1()  asm volatile("cp.async.wait_group 1;" ::: "memory")
#define CP_WAIT0()  asm volatile("cp.async.wait_group 0;" ::: "memory")

// Split two fp32 -> (hi bf16x2 truncation, mid bf16x2 rn).
__device__ __forceinline__ void split2(float x, float y,
                                       uint32_t& hi, uint32_t& mid) {
    uint32_t ux = __float_as_uint(x), uy = __float_as_uint(y);
    hi = __byte_perm(ux, uy, 0x7632);
    float fx = x - __uint_as_float(ux & 0xFFFF0000u);
    float fy = y - __uint_as_float(uy & 0xFFFF0000u);
    __nv_bfloat162 m = __floats2bfloat162_rn(fx, fy);
    mid = *(uint32_t*)&m;
}

__global__ __launch_bounds__(256) void prep_w(const float* __restrict__ W) {
    int idx = blockIdx.x * 256 + threadIdx.x;   // 32768
    int k = idx >> 7;
    int n = idx & 127;
    float x = W[idx];
    uint32_t ux = __float_as_uint(x);
    float mid = x - __uint_as_float(ux & 0xFFFF0000u);
    g_whi [n * KTOT + k] = __ushort_as_bfloat16((unsigned short)(ux >> 16));
    g_wmid[n * KTOT + k] = __float2bfloat16(mid);
}

__global__ __launch_bounds__(512, 1) void sgl_gemm_mma(
    const float* __restrict__ A,   // [M, 256]
    float* __restrict__ H,         // [M, 128]
    int M)
{
    extern __shared__ char smem[];
    const uint32_t sbase = (uint32_t)__cvta_generic_to_shared(smem);

    const int tid  = threadIdx.x;
    const int wid  = tid >> 5;
    const int lane = tid & 31;
    const int g    = lane >> 2;
    const int t    = lane & 3;
    const int m0w  = (wid >> 2) * 32;
    const int n0w  = (wid & 3) * 32;
    const int row0 = blockIdx.x * MTILE;

    // ldmatrix lane mappings (byte offsets; shared-space asm only)
    const int aRow  = (lane & 7) + ((lane >> 3) & 1) * 8;
    const int aKw   = (lane >> 4) * 4;
    const int baseA0 = ((m0w + aRow) * LDS_W + aKw) * 4;
    const int baseA1 = ((m0w + 16 + aRow) * LDS_W + aKw) * 4;
    const int bRow  = lane & 7;
    const int bNt   = lane >> 4;
    const int bKw   = ((lane >> 3) & 1) * 4;
    const int baseB0 = ((n0w + (0 + bNt) * 8 + bRow) * LDS_W + bKw) * 4;
    const int baseB1 = ((n0w + (2 + bNt) * 8 + bRow) * LDS_W + bKw) * 4;

    // staging decompositions
    const int sAr = tid >> 4;           // A-stage: row 0..31?? (recomputed below)
    (void)sAr;

    float acc[2][4][4];
#pragma unroll
    for (int mt = 0; mt < 2; ++mt)
#pragma unroll
        for (int nt = 0; nt < 4; ++nt)
#pragma unroll
            for (int j = 0; j < 4; ++j) acc[mt][nt][j] = 0.f;

    const int ar = tid >> 2;            // convert-phase row
    const int at = tid & 3;
    const int aw0base = ar * LDS_W + at * 8;   // split-tile word offset

    // ---- stage helper (inlined twice via lambda) ----
    auto stage = [&](int ch, int p) {
        const int k0 = ch * KCH;
        // A raw: 2048 16B chunks (128 rows x 16 chunks)
#pragma unroll
        for (int s = 0; s < 4; ++s) {
            int idx = tid + s * 512;
            int r = idx >> 4;
            int q = idx & 15;
            uint32_t dst = sbase + S_ARAW0 + p * ARAW_BUF + (r * ARAW_W + q * 4) * 4;
            const float* src = A + (size_t)(row0 + r) * KTOT + k0 + q * 4;
            cp16(dst, src, (row0 + r) < M ? 16 : 0);
        }
        // B tiles: 2048 16B chunks (2 splits x 128 rows x 8 chunks)
#pragma unroll
        for (int s = 0; s < 4; ++s) {
            int idx = tid + s * 512;
            int split = idx >> 10;
            int r = (idx >> 3) & 127;
            int q = idx & 7;
            uint32_t dst = sbase + S_BT0 + p * B_BUF + split * B_MID
                         + r * (LDS_W * 4) + q * 16;
            const __nv_bfloat16* srcb =
                (split ? g_wmid : g_whi) + (size_t)r * KTOT + k0 + q * 8;
            cp16(dst, srcb, 16);
        }
        CP_COMMIT();
    };

    // ---- prologue: stage chunks 0 and 1 ----
    stage(0, 0);
    stage(1, 1);

    for (int ch = 0; ch < 4; ++ch) {
        const int p = ch & 1;

        if (ch < 3) CP_WAIT1(); else CP_WAIT0();
        __syncthreads();

        // ---- convert A raw -> split tiles (smem -> smem) ----
        {
            const float4* rawrow = (const float4*)(smem + S_ARAW0 + p * ARAW_BUF
                                                   + ar * (ARAW_W * 4));
            uint32_t* dsthi = (uint32_t*)(smem + S_AHI);
            uint32_t* dstmi = (uint32_t*)(smem + S_AMID);
#pragma unroll
            for (int j = 0; j < 4; ++j) {
                float4 v = rawrow[at * 4 + j];
                uint32_t h0, mm0, h1, mm1;
                split2(v.x, v.y, h0, mm0);
                split2(v.z, v.w, h1, mm1);
                *(uint2*)(dsthi + aw0base + j * 2) = make_uint2(h0, h1);
                *(uint2*)(dstmi + aw0base + j * 2) = make_uint2(mm0, mm1);
            }
        }
        __syncthreads();

        // ---- MMA over 4 k-steps ----
        const uint32_t bHi = sbase + S_BT0 + p * B_BUF;
        const uint32_t bMi = bHi + B_MID;
#pragma unroll
        for (int ks = 0; ks < 4; ++ks) {
            const int kw = ks * 32;

            uint32_t afr[2][2][4];
            ldsm4(afr[0][0], sbase + S_AHI  + baseA0 + kw);
            ldsm4(afr[0][1], sbase + S_AHI  + baseA1 + kw);
            ldsm4(afr[1][0], sbase + S_AMID + baseA0 + kw);
            ldsm4(afr[1][1], sbase + S_AMID + baseA1 + kw);

            uint32_t bfr[2][8];
            ldsm4(&bfr[0][0], bHi + baseB0 + kw);
            ldsm4(&bfr[0][4], bHi + baseB1 + kw);
            ldsm4(&bfr[1][0], bMi + baseB0 + kw);
            ldsm4(&bfr[1][4], bMi + baseB1 + kw);

#pragma unroll
            for (int mt = 0; mt < 2; ++mt)
#pragma unroll
                for (int nt = 0; nt < 4; ++nt) {
                    mma_bf16(acc[mt][nt], afr[0][mt], &bfr[0][nt * 2]);  // hi*hi
                    mma_bf16(acc[mt][nt], afr[0][mt], &bfr[1][nt * 2]);  // hi*mid
                    mma_bf16(acc[mt][nt], afr[1][mt], &bfr[0][nt * 2]);  // mid*hi
                }
        }
        __syncthreads();

        // stage chunk ch+2 into buffer p (now free)
        if (ch < 2) stage(ch + 2, p);
    }

    // ---- Epilogue: fp32 H + fp16 shadow ----
#pragma unroll
    for (int mt = 0; mt < 2; ++mt)
#pragma unroll
        for (int nt = 0; nt < 4; ++nt) {
            int row = row0 + m0w + mt * 16 + g;
            int col = n0w + nt * 8 + t * 2;
            if (row < M) {
                *(float2*)(H + (size_t)row * NTOT + col) =
                    make_float2(acc[mt][nt][0], acc[mt][nt][1]);
                *(__half2*)(g_h16 + (size_t)row * NTOT + col) =
                    __floats2half2_rn(acc[mt][nt][0], acc[mt][nt][1]);
            }
            if (row + 8 < M) {
                *(float2*)(H + (size_t)(row + 8) * NTOT + col) =
                    make_float2(acc[mt][nt][2], acc[mt][nt][3]);
                *(__half2*)(g_h16 + (size_t)(row + 8) * NTOT + col) =
                    __floats2half2_rn(acc[mt][nt][2], acc[mt][nt][3]);
            }
        }
}

// ---------------------------------------------------------------------------
// Edge kernel on fp16 shadow: 8 lanes/edge, 4 edges/warp.
// ---------------------------------------------------------------------------
__device__ __forceinline__ float dot8_absdiff(uint4 x, uint4 y,
                                              float4 a0, float4 a1) {
    float2 fx0 = __half22float2(*(__half2*)&x.x), fy0 = __half22float2(*(__half2*)&y.x);
    float2 fx1 = __half22float2(*(__half2*)&x.y), fy1 = __half22float2(*(__half2*)&y.y);
    float2 fx2 = __half22float2(*(__half2*)&x.z), fy2 = __half22float2(*(__half2*)&y.z);
    float2 fx3 = __half22float2(*(__half2*)&x.w), fy3 = __half22float2(*(__half2*)&y.w);
    float s;
    s  = fabsf(fx0.x - fy0.x) * a0.x;
    s += fabsf(fx0.y - fy0.y) * a0.y;
    s += fabsf(fx1.x - fy1.x) * a0.z;
    s += fabsf(fx1.y - fy1.y) * a0.w;
    s += fabsf(fx2.x - fy2.x) * a1.x;
    s += fabsf(fx2.y - fy2.y) * a1.y;
    s += fabsf(fx3.x - fy3.x) * a1.z;
    s += fabsf(fx3.y - fy3.y) * a1.w;
    return s;
}

__global__ __launch_bounds__(256) void sgl_edge_kernel(
    const int* __restrict__ edge,
    const float* __restrict__ a,
    float* __restrict__ out,
    int E)
{
    const int lane = threadIdx.x & 31;
    const int g = lane >> 3;
    const int l = lane & 7;

    float4 aA0 = *(const float4*)(a +      8 * l);
    float4 aA1 = *(const float4*)(a +      8 * l + 4);
    float4 aB0 = *(const float4*)(a + 64 + 8 * l);
    float4 aB1 = *(const float4*)(a + 64 + 8 * l + 4);

    const int warp_id = blockIdx.x * (blockDim.x >> 5) + (threadIdx.x >> 5);
    const int nwarps  = gridDim.x * (blockDim.x >> 5);
    const int nquads  = (E + 3) >> 2;

    for (int quad = warp_id; quad < nquads; quad += nwarps) {
        int e = quad * 4 + g;
        bool valid = e < E;
        int ec = valid ? e : 0;

        int u = edge[ec];
        int v = edge[(size_t)E + ec];

        const uint4* xp = (const uint4*)(g_h16 + (size_t)u * NTOT) + l;
        const uint4* yp = (const uint4*)(g_h16 + (size_t)v * NTOT) + l;

        uint4 x0 = xp[0], x1 = xp[8];
        uint4 y0 = yp[0], y1 = yp[8];

        float s = dot8_absdiff(x0, y0, aA0, aA1)
                + dot8_absdiff(x1, y1, aB0, aB1);

        s += __shfl_xor_sync(0xffffffffu, s, 1);
        s += __shfl_xor_sync(0xffffffffu, s, 2);
        s += __shfl_xor_sync(0xffffffffu, s, 4);

        if (l == 0 && valid) out[e] = fmaxf(s, 0.f);
    }
}

extern "C" void kernel_launch(void* const* d_in, const int* in_sizes, int n_in,
                              void* d_out, int out_size)
{
    const float* A    = (const float*)d_in[0];
    const int*   edge = (const int*)d_in[1];
    const float* W    = (const float*)d_in[2];
    const float* a    = (const float*)d_in[3];

    const int M = in_sizes[0] / KTOT;
    const int E = in_sizes[1] / 2;

    float* H  = (float*)d_out;
    float* ew = (float*)d_out + (size_t)M * NTOT;

    cudaFuncSetAttribute(sgl_gemm_mma,
                         cudaFuncAttributeMaxDynamicSharedMemorySize, S_TOTAL);

    prep_w<<<128, 256>>>(W);

    int gemm_blocks = (M + MTILE - 1) / MTILE;
    sgl_gemm_mma<<<gemm_blocks, 512, S_TOTAL>>>(A, H, M);

    int edge_blocks = 2048;
    sgl_edge_kernel<<<edge_blocks, 256>>>(edge, a, ew, E);
}

// round 13
// speedup vs baseline: 1.1504x; 1.1504x over previous
#include <cuda_runtime.h>
#include <cuda_bf16.h>
#include <cuda_fp16.h>
#include <cstdint>
#include <cstddef>

// ---------------------------------------------------------------------------
// SparseGraphLearn:
//   h = inputs @ weight          [M=100000,256] @ [256,128]  fp32
//   edge_weight = relu(|h[e0]-h[e1]| @ a)   [E]
// d_out = [ h | edge_weight ]
//
// GEMM: mma.sync m16n8k16 bf16, truncation 2-term split (3 cross products).
//   MTILE=64, 256 threads, 2 CTAs/SM -> convert/copy phases of one CTA
//   overlap MMA of the co-resident CTA.
// Edge: gathers from fp16 shadow of h.
// ---------------------------------------------------------------------------

#define KTOT 256
#define NTOT 128
#define MTILE 64
#define KCH 64
#define LDS_W 36          // row stride in words (4 mod 32 -> conflict-free)
#define NMAX 100000

// smem layout (bytes)
#define SA_HI  0
#define SA_MID 9216                   // 64*36*4
#define SB_HI  18432
#define SB_MID 36864                  // + 128*36*4
#define S_TOTAL 55296

__device__ __nv_bfloat16 g_whi[NTOT * KTOT];   // [n][k]
__device__ __nv_bfloat16 g_wmid[NTOT * KTOT];
__device__ __half        g_h16[(size_t)NMAX * NTOT];

__device__ __forceinline__ void mma_bf16(float* d, const uint32_t* a, const uint32_t* b) {
    asm volatile(
        "mma.sync.aligned.m16n8k16.row.col.f32.bf16.bf16.f32 "
        "{%0,%1,%2,%3}, {%4,%5,%6,%7}, {%8,%9}, {%0,%1,%2,%3};"
        : "+f"(d[0]), "+f"(d[1]), "+f"(d[2]), "+f"(d[3])
        : "r"(a[0]), "r"(a[1]), "r"(a[2]), "r"(a[3]), "r"(b[0]), "r"(b[1]));
}

__device__ __forceinline__ void ldsm4(uint32_t* r, uint32_t addr) {
    asm volatile("ldmatrix.sync.aligned.m8n8.x4.shared.b16 {%0,%1,%2,%3}, [%4];"
        : "=r"(r[0]), "=r"(r[1]), "=r"(r[2]), "=r"(r[3]) : "r"(addr));
}

// Split two fp32 -> (hi bf16x2 truncation, mid bf16x2 rn).
__device__ __forceinline__ void split2(float x, float y,
                                       uint32_t& hi, uint32_t& mid) {
    uint32_t ux = __float_as_uint(x), uy = __float_as_uint(y);
    hi = __byte_perm(ux, uy, 0x7632);
    float fx = x - __uint_as_float(ux & 0xFFFF0000u);
    float fy = y - __uint_as_float(uy & 0xFFFF0000u);
    __nv_bfloat162 m = __floats2bfloat162_rn(fx, fy);
    mid = *(uint32_t*)&m;
}

__global__ __launch_bounds__(256) void prep_w(const float* __restrict__ W) {
    int idx = blockIdx.x * 256 + threadIdx.x;   // 32768
    int k = idx >> 7;
    int n = idx & 127;
    float x = W[idx];
    uint32_t ux = __float_as_uint(x);
    float mid = x - __uint_as_float(ux & 0xFFFF0000u);
    g_whi [n * KTOT + k] = __ushort_as_bfloat16((unsigned short)(ux >> 16));
    g_wmid[n * KTOT + k] = __float2bfloat16(mid);
}

__global__ __launch_bounds__(256, 2) void sgl_gemm_mma(
    const float* __restrict__ A,   // [M, 256]
    float* __restrict__ H,         // [M, 128]
    int M)
{
    extern __shared__ char smem[];
    uint32_t* sAhi = (uint32_t*)(smem + SA_HI);
    uint32_t* sAmi = (uint32_t*)(smem + SA_MID);
    uint32_t* sBhi = (uint32_t*)(smem + SB_HI);
    uint32_t* sBmi = (uint32_t*)(smem + SB_MID);
    const uint32_t sbase = (uint32_t)__cvta_generic_to_shared(smem);

    const int tid  = threadIdx.x;
    const int wid  = tid >> 5;          // 0..7
    const int lane = tid & 31;
    const int g    = lane >> 2;
    const int t    = lane & 3;
    const int m0w  = (wid >> 2) * 32;   // 0 or 32
    const int n0w  = (wid & 3) * 32;    // 0,32,64,96
    const int row0 = blockIdx.x * MTILE;

    // ldmatrix lane mappings (byte offsets; shared-space asm only)
    const int aRow  = (lane & 7) + ((lane >> 3) & 1) * 8;
    const int aKw   = (lane >> 4) * 4;
    const int baseA0 = ((m0w + aRow) * LDS_W + aKw) * 4;
    const int baseA1 = ((m0w + 16 + aRow) * LDS_W + aKw) * 4;
    const int bRow  = lane & 7;
    const int bNt   = lane >> 4;
    const int bKw   = ((lane >> 3) & 1) * 4;
    const int baseB0 = ((n0w + (0 + bNt) * 8 + bRow) * LDS_W + bKw) * 4;
    const int baseB1 = ((n0w + (2 + bNt) * 8 + bRow) * LDS_W + bKw) * 4;

    float acc[2][4][4];
#pragma unroll
    for (int mt = 0; mt < 2; ++mt)
#pragma unroll
        for (int nt = 0; nt < 4; ++nt)
#pragma unroll
            for (int j = 0; j < 4; ++j) acc[mt][nt][j] = 0.f;

    const int ar = tid >> 2;            // A row within tile (0..63)
    const int at = tid & 3;
    const bool arok = (row0 + ar) < M;
    const float4* arow = (const float4*)(A + (size_t)(row0 + ar) * KTOT);
    const int aw0base = ar * LDS_W + at * 8;

    float4 v[4];
    // prologue: chunk 0
#pragma unroll
    for (int j = 0; j < 4; ++j)
        v[j] = arok ? arow[at * 4 + j] : make_float4(0.f, 0.f, 0.f, 0.f);

    for (int ch = 0; ch < 4; ++ch) {
        const int k0 = ch * KCH;

        // ---- convert + store A chunk ----
#pragma unroll
        for (int j = 0; j < 4; ++j) {
            uint32_t h0, mm0, h1, mm1;
            split2(v[j].x, v[j].y, h0, mm0);
            split2(v[j].z, v[j].w, h1, mm1);
            int w0 = aw0base + j * 2;
            *(uint2*)(sAhi + w0) = make_uint2(h0, h1);
            *(uint2*)(sAmi + w0) = make_uint2(mm0, mm1);
        }

        // ---- B chunk copy from pre-split global (2048 uint2, 8/thread) ----
#pragma unroll
        for (int s = 0; s < 8; ++s) {
            int idx = tid + s * 256;
            int r = idx >> 4;
            int q = idx & 15;
            *(uint2*)(sBhi + r * LDS_W + q * 2) =
                *((const uint2*)(g_whi + (size_t)r * KTOT + k0) + q);
            *(uint2*)(sBmi + r * LDS_W + q * 2) =
                *((const uint2*)(g_wmid + (size_t)r * KTOT + k0) + q);
        }
        __syncthreads();

        // ---- prefetch next A chunk ----
        if (ch < 3) {
            const float4* src = arow + (ch + 1) * (KCH / 4) + at * 4;
#pragma unroll
            for (int j = 0; j < 4; ++j)
                v[j] = arok ? src[j] : make_float4(0.f, 0.f, 0.f, 0.f);
        }

        // ---- MMA over 4 k-steps ----
#pragma unroll
        for (int ks = 0; ks < 4; ++ks) {
            const int kw = ks * 32;

            uint32_t afr[2][2][4];
            ldsm4(afr[0][0], sbase + SA_HI  + baseA0 + kw);
            ldsm4(afr[0][1], sbase + SA_HI  + baseA1 + kw);
            ldsm4(afr[1][0], sbase + SA_MID + baseA0 + kw);
            ldsm4(afr[1][1], sbase + SA_MID + baseA1 + kw);

            uint32_t bfr[2][8];
            ldsm4(&bfr[0][0], sbase + SB_HI  + baseB0 + kw);
            ldsm4(&bfr[0][4], sbase + SB_HI  + baseB1 + kw);
            ldsm4(&bfr[1][0], sbase + SB_MID + baseB0 + kw);
            ldsm4(&bfr[1][4], sbase + SB_MID + baseB1 + kw);

#pragma unroll
            for (int mt = 0; mt < 2; ++mt)
#pragma unroll
                for (int nt = 0; nt < 4; ++nt) {
                    mma_bf16(acc[mt][nt], afr[0][mt], &bfr[0][nt * 2]);  // hi*hi
                    mma_bf16(acc[mt][nt], afr[0][mt], &bfr[1][nt * 2]);  // hi*mid
                    mma_bf16(acc[mt][nt], afr[1][mt], &bfr[0][nt * 2]);  // mid*hi
                }
        }
        __syncthreads();
    }

    // ---- Epilogue: fp32 H + fp16 shadow ----
#pragma unroll
    for (int mt = 0; mt < 2; ++mt)
#pragma unroll
        for (int nt = 0; nt < 4; ++nt) {
            int row = row0 + m0w + mt * 16 + g;
            int col = n0w + nt * 8 + t * 2;
            if (row < M) {
                *(float2*)(H + (size_t)row * NTOT + col) =
                    make_float2(acc[mt][nt][0], acc[mt][nt][1]);
                *(__half2*)(g_h16 + (size_t)row * NTOT + col) =
                    __floats2half2_rn(acc[mt][nt][0], acc[mt][nt][1]);
            }
            if (row + 8 < M) {
                *(float2*)(H + (size_t)(row + 8) * NTOT + col) =
                    make_float2(acc[mt][nt][2], acc[mt][nt][3]);
                *(__half2*)(g_h16 + (size_t)(row + 8) * NTOT + col) =
                    __floats2half2_rn(acc[mt][nt][2], acc[mt][nt][3]);
            }
        }
}

// ---------------------------------------------------------------------------
// Edge kernel on fp16 shadow: 8 lanes/edge, 4 edges/warp.
// ---------------------------------------------------------------------------
__device__ __forceinline__ float dot8_absdiff(uint4 x, uint4 y,
                                              float4 a0, float4 a1) {
    float2 fx0 = __half22float2(*(__half2*)&x.x), fy0 = __half22float2(*(__half2*)&y.x);
    float2 fx1 = __half22float2(*(__half2*)&x.y), fy1 = __half22float2(*(__half2*)&y.y);
    float2 fx2 = __half22float2(*(__half2*)&x.z), fy2 = __half22float2(*(__half2*)&y.z);
    float2 fx3 = __half22float2(*(__half2*)&x.w), fy3 = __half22float2(*(__half2*)&y.w);
    float s;
    s  = fabsf(fx0.x - fy0.x) * a0.x;
    s += fabsf(fx0.y - fy0.y) * a0.y;
    s += fabsf(fx1.x - fy1.x) * a0.z;
    s += fabsf(fx1.y - fy1.y) * a0.w;
    s += fabsf(fx2.x - fy2.x) * a1.x;
    s += fabsf(fx2.y - fy2.y) * a1.y;
    s += fabsf(fx3.x - fy3.x) * a1.z;
    s += fabsf(fx3.y - fy3.y) * a1.w;
    return s;
}

__global__ __launch_bounds__(256) void sgl_edge_kernel(
    const int* __restrict__ edge,
    const float* __restrict__ a,
    float* __restrict__ out,
    int E)
{
    const int lane = threadIdx.x & 31;
    const int g = lane >> 3;
    const int l = lane & 7;

    float4 aA0 = *(const float4*)(a +      8 * l);
    float4 aA1 = *(const float4*)(a +      8 * l + 4);
    float4 aB0 = *(const float4*)(a + 64 + 8 * l);
    float4 aB1 = *(const float4*)(a + 64 + 8 * l + 4);

    const int warp_id = blockIdx.x * (blockDim.x >> 5) + (threadIdx.x >> 5);
    const int nwarps  = gridDim.x * (blockDim.x >> 5);
    const int nquads  = (E + 3) >> 2;

    for (int quad = warp_id; quad < nquads; quad += nwarps) {
        int e = quad * 4 + g;
        bool valid = e < E;
        int ec = valid ? e : 0;

        int u = edge[ec];
        int v = edge[(size_t)E + ec];

        const uint4* xp = (const uint4*)(g_h16 + (size_t)u * NTOT) + l;
        const uint4* yp = (const uint4*)(g_h16 + (size_t)v * NTOT) + l;

        uint4 x0 = xp[0], x1 = xp[8];
        uint4 y0 = yp[0], y1 = yp[8];

        float s = dot8_absdiff(x0, y0, aA0, aA1)
                + dot8_absdiff(x1, y1, aB0, aB1);

        s += __shfl_xor_sync(0xffffffffu, s, 1);
        s += __shfl_xor_sync(0xffffffffu, s, 2);
        s += __shfl_xor_sync(0xffffffffu, s, 4);

        if (l == 0 && valid) out[e] = fmaxf(s, 0.f);
    }
}

extern "C" void kernel_launch(void* const* d_in, const int* in_sizes, int n_in,
                              void* d_out, int out_size)
{
    const float* A    = (const float*)d_in[0];
    const int*   edge = (const int*)d_in[1];
    const float* W    = (const float*)d_in[2];
    const float* a    = (const float*)d_in[3];

    const int M = in_sizes[0] / KTOT;
    const int E = in_sizes[1] / 2;

    float* H  = (float*)d_out;
    float* ew = (float*)d_out + (size_t)M * NTOT;

    cudaFuncSetAttribute(sgl_gemm_mma,
                         cudaFuncAttributeMaxDynamicSharedMemorySize, S_TOTAL);

    prep_w<<<128, 256>>>(W);

    int gemm_blocks = (M + MTILE - 1) / MTILE;
    sgl_gemm_mma<<<gemm_blocks, 256, S_TOTAL>>>(A, H, M);

    int edge_blocks = 2048;
    sgl_edge_kernel<<<edge_blocks, 256>>>(edge, a, ew, E);
}